// round 1
// baseline (speedup 1.0000x reference)
#include <cuda_runtime.h>
#include <cstdint>

// Problem shape (fixed by the dataset)
#define M_TOK 16384   // B*S tokens
#define K_DIM 2048    // DIN
#define N_DIM 2048    // DOUT

// ---------------------------------------------------------------------------
// Scratch (no allocations allowed -> __device__ globals)
// ---------------------------------------------------------------------------
__device__ int8_t g_xq[(size_t)M_TOK * K_DIM];      // 32 MB quantized activations
__device__ float  g_xscale[M_TOK];                  // per-token scale
__device__ int8_t g_w[(size_t)N_DIM * K_DIM];       // 4 MB ternary weights as int8
__device__ int    g_acc[(size_t)M_TOK * N_DIM];     // 128 MB int32 GEMM output

// ---------------------------------------------------------------------------
// Kernel 0: repack ternary int32 weights -> int8
// ---------------------------------------------------------------------------
__global__ void pack_w_kernel(const int* __restrict__ wt) {
    int idx = blockIdx.x * blockDim.x + threadIdx.x;    // group of 4 elements
    if (idx >= (N_DIM * K_DIM) / 4) return;
    int4 v = ((const int4*)wt)[idx];
    char4 c;
    c.x = (char)v.x; c.y = (char)v.y; c.z = (char)v.z; c.w = (char)v.w;
    ((char4*)g_w)[idx] = c;
}

// ---------------------------------------------------------------------------
// Block reductions (256 threads)
// ---------------------------------------------------------------------------
__device__ __forceinline__ float2 block_reduce_sum2(float a, float b, float* sh) {
    #pragma unroll
    for (int o = 16; o > 0; o >>= 1) {
        a += __shfl_xor_sync(0xFFFFFFFFu, a, o);
        b += __shfl_xor_sync(0xFFFFFFFFu, b, o);
    }
    int w = threadIdx.x >> 5, l = threadIdx.x & 31;
    if (l == 0) { sh[w] = a; sh[w + 8] = b; }
    __syncthreads();
    if (threadIdx.x < 32) {
        float va = (l < 8) ? sh[l] : 0.f;
        float vb = (l < 8) ? sh[l + 8] : 0.f;
        #pragma unroll
        for (int o = 4; o > 0; o >>= 1) {
            va += __shfl_xor_sync(0xFFFFFFFFu, va, o);
            vb += __shfl_xor_sync(0xFFFFFFFFu, vb, o);
        }
        if (l == 0) { sh[16] = va; sh[17] = vb; }
    }
    __syncthreads();
    float2 r = make_float2(sh[16], sh[17]);
    __syncthreads();
    return r;
}

__device__ __forceinline__ float block_reduce_max(float v, float* sh) {
    #pragma unroll
    for (int o = 16; o > 0; o >>= 1)
        v = fmaxf(v, __shfl_xor_sync(0xFFFFFFFFu, v, o));
    int w = threadIdx.x >> 5, l = threadIdx.x & 31;
    if (l == 0) sh[w] = v;
    __syncthreads();
    if (threadIdx.x < 32) {
        float m = (l < 8) ? sh[l] : -1e30f;
        #pragma unroll
        for (int o = 4; o > 0; o >>= 1)
            m = fmaxf(m, __shfl_xor_sync(0xFFFFFFFFu, m, o));
        if (l == 0) sh[16] = m;
    }
    __syncthreads();
    float r = sh[16];
    __syncthreads();
    return r;
}

// ---------------------------------------------------------------------------
// Kernel 1: fused input LayerNorm + per-token int8 absmax quantization.
// One block (256 threads) per token row; 8 elements/thread stay in registers.
// ---------------------------------------------------------------------------
__global__ __launch_bounds__(256) void ln_quant_kernel(const float* __restrict__ x) {
    __shared__ float sh[18];
    const int row = blockIdx.x;
    const int t = threadIdx.x;
    const float4* xr = (const float4*)(x + (size_t)row * K_DIM);

    float v[8];
    float4 a = xr[t];
    float4 b = xr[t + 256];
    v[0]=a.x; v[1]=a.y; v[2]=a.z; v[3]=a.w;
    v[4]=b.x; v[5]=b.y; v[6]=b.z; v[7]=b.w;

    float s = 0.f, ss = 0.f;
    #pragma unroll
    for (int i = 0; i < 8; i++) { s += v[i]; ss += v[i]*v[i]; }
    float2 tot = block_reduce_sum2(s, ss, sh);

    const float invn = 1.0f / (float)K_DIM;
    float mu  = tot.x * invn;
    float var = fmaxf(tot.y * invn - mu * mu, 0.f);   // biased variance (torch default)
    float rstd = rsqrtf(var + 1e-5f);

    float amax = 0.f;
    #pragma unroll
    for (int i = 0; i < 8; i++) {
        v[i] = (v[i] - mu) * rstd;
        amax = fmaxf(amax, fabsf(v[i]));
    }
    amax = block_reduce_max(amax, sh);
    amax = fmaxf(amax, 1e-5f);
    float scale = amax * (1.0f / 127.0f);
    float inv   = 127.0f / amax;

    char q[8];
    #pragma unroll
    for (int i = 0; i < 8; i++) {
        int qi = (int)rintf(v[i] * inv);       // round-half-even, matches jnp.round
        qi = max(-127, min(127, qi));
        q[i] = (char)qi;
    }
    char4* dst = (char4*)(g_xq + (size_t)row * K_DIM);
    char4 c0; c0.x=q[0]; c0.y=q[1]; c0.z=q[2]; c0.w=q[3];
    char4 c1; c1.x=q[4]; c1.y=q[5]; c1.z=q[6]; c1.w=q[7];
    dst[t] = c0;
    dst[t + 256] = c1;
    if (t == 0) g_xscale[row] = scale;
}

// ---------------------------------------------------------------------------
// Kernel 2: int8 dp4a GEMM.  acc[m][n] = sum_k xq[m][k] * w[n][k]
// Tile: BM=128, BN=128, BK=64 int8 (16 dp4a words). 256 threads, 8x8 micro-tile.
// ---------------------------------------------------------------------------
#define BM  128
#define BN  128
#define BKB 64    // K-bytes per tile
#define BKW 16    // K-words per tile

__global__ __launch_bounds__(256) void gemm_kernel() {
    __shared__ uint32_t sA[BKW][BM];
    __shared__ uint32_t sB[BKW][BN];

    const int bm = blockIdx.y * BM;
    const int bn = blockIdx.x * BN;
    const int tid = threadIdx.x;
    const int tx = tid & 15;          // n-direction
    const int ty = tid >> 4;          // m-direction

    int acc[8][8];
    #pragma unroll
    for (int i = 0; i < 8; i++)
        #pragma unroll
        for (int j = 0; j < 8; j++) acc[i][j] = 0;

    for (int k0 = 0; k0 < K_DIM; k0 += BKB) {
        // cooperative load: 128 rows x 64B per tile per matrix = 512 uint4; 2/thread
        #pragma unroll
        for (int l = 0; l < 2; l++) {
            int idx = tid * 2 + l;          // 0..511
            int row = idx >> 2;             // 0..127
            int w4  = idx & 3;              // which 16B chunk
            uint4 va = *(const uint4*)(g_xq + (size_t)(bm + row) * K_DIM + k0 + w4 * 16);
            sA[w4*4+0][row] = va.x; sA[w4*4+1][row] = va.y;
            sA[w4*4+2][row] = va.z; sA[w4*4+3][row] = va.w;
            uint4 vb = *(const uint4*)(g_w + (size_t)(bn + row) * K_DIM + k0 + w4 * 16);
            sB[w4*4+0][row] = vb.x; sB[w4*4+1][row] = vb.y;
            sB[w4*4+2][row] = vb.z; sB[w4*4+3][row] = vb.w;
        }
        __syncthreads();

        #pragma unroll
        for (int kw = 0; kw < BKW; kw++) {
            uint32_t aF[8], bF[8];
            *(uint4*)&aF[0] = *(const uint4*)&sA[kw][ty * 8];
            *(uint4*)&aF[4] = *(const uint4*)&sA[kw][ty * 8 + 4];
            *(uint4*)&bF[0] = *(const uint4*)&sB[kw][tx * 8];
            *(uint4*)&bF[4] = *(const uint4*)&sB[kw][tx * 8 + 4];
            #pragma unroll
            for (int i = 0; i < 8; i++)
                #pragma unroll
                for (int j = 0; j < 8; j++)
                    acc[i][j] = __dp4a((int)aF[i], (int)bF[j], acc[i][j]);
        }
        __syncthreads();
    }

    #pragma unroll
    for (int i = 0; i < 8; i++) {
        int grow = bm + ty * 8 + i;
        int4* dst = (int4*)(g_acc + (size_t)grow * N_DIM + bn + tx * 8);
        int4 o0; o0.x=acc[i][0]; o0.y=acc[i][1]; o0.z=acc[i][2]; o0.w=acc[i][3];
        int4 o1; o1.x=acc[i][4]; o1.y=acc[i][5]; o1.z=acc[i][6]; o1.w=acc[i][7];
        dst[0] = o0;
        dst[1] = o1;
    }
}

// ---------------------------------------------------------------------------
// Kernel 3: fused dequant (x_scale[t] * w_scale[o]) + output LayerNorm.
// One block (256 threads) per token row.
// ---------------------------------------------------------------------------
__global__ __launch_bounds__(256) void ln_out_kernel(const float* __restrict__ wscale,
                                                     float* __restrict__ out) {
    __shared__ float sh[18];
    const int row = blockIdx.x;
    const int t = threadIdx.x;
    const float s_t = g_xscale[row];

    const int4* ar = (const int4*)(g_acc + (size_t)row * N_DIM);
    const float4* ws = (const float4*)wscale;

    int4 a = ar[t];
    int4 b = ar[t + 256];
    float4 w0 = __ldg(&ws[t]);
    float4 w1 = __ldg(&ws[t + 256]);

    float v[8];
    v[0] = (float)a.x * s_t * w0.x;
    v[1] = (float)a.y * s_t * w0.y;
    v[2] = (float)a.z * s_t * w0.z;
    v[3] = (float)a.w * s_t * w0.w;
    v[4] = (float)b.x * s_t * w1.x;
    v[5] = (float)b.y * s_t * w1.y;
    v[6] = (float)b.z * s_t * w1.z;
    v[7] = (float)b.w * s_t * w1.w;

    float s = 0.f, ss = 0.f;
    #pragma unroll
    for (int i = 0; i < 8; i++) { s += v[i]; ss += v[i]*v[i]; }
    float2 tot = block_reduce_sum2(s, ss, sh);

    const float invn = 1.0f / (float)N_DIM;
    float mu  = tot.x * invn;
    float var = fmaxf(tot.y * invn - mu * mu, 0.f);
    float rstd = rsqrtf(var + 1e-5f);

    float4* dst = (float4*)(out + (size_t)row * N_DIM);
    float4 o0, o1;
    o0.x = (v[0]-mu)*rstd; o0.y = (v[1]-mu)*rstd;
    o0.z = (v[2]-mu)*rstd; o0.w = (v[3]-mu)*rstd;
    o1.x = (v[4]-mu)*rstd; o1.y = (v[5]-mu)*rstd;
    o1.z = (v[6]-mu)*rstd; o1.w = (v[7]-mu)*rstd;
    dst[t] = o0;
    dst[t + 256] = o1;
}

// ---------------------------------------------------------------------------
// Launch
// ---------------------------------------------------------------------------
extern "C" void kernel_launch(void* const* d_in, const int* in_sizes, int n_in,
                              void* d_out, int out_size) {
    const float* x  = (const float*)d_in[0];          // [4,4096,2048] f32
    const int*   wt = (const int*)d_in[1];            // [2048,2048] i32 ternary
    const float* ws = (const float*)d_in[2];          // [2048] f32
    float* out = (float*)d_out;                       // [4,4096,2048] f32

    pack_w_kernel<<<(N_DIM * K_DIM / 4 + 255) / 256, 256>>>(wt);
    ln_quant_kernel<<<M_TOK, 256>>>(x);
    dim3 grid(N_DIM / BN, M_TOK / BM);                // (16, 128)
    gemm_kernel<<<grid, 256>>>();
    ln_out_kernel<<<M_TOK, 256>>>(ws, out);
}

// round 4
// speedup vs baseline: 3.8279x; 3.8279x over previous
#include <cuda_runtime.h>
#include <cuda_bf16.h>
#include <cstdint>

#define M_TOK 16384   // B*S tokens
#define K_DIM 2048    // DIN
#define N_DIM 2048    // DOUT

// ---------------------------------------------------------------------------
// Scratch (__device__ globals; no allocations allowed)
// ---------------------------------------------------------------------------
__device__ int8_t g_xq[(size_t)M_TOK * K_DIM];      // 32 MB quantized activations
__device__ float  g_xscale[M_TOK];                  // per-token scale
__device__ int8_t g_w[(size_t)N_DIM * K_DIM];       // 4 MB ternary weights as int8
__device__ int    g_acc[(size_t)M_TOK * N_DIM];     // 128 MB int32 GEMM output

// ---------------------------------------------------------------------------
// Kernel 0: repack ternary int32 weights -> int8
// ---------------------------------------------------------------------------
__global__ void pack_w_kernel(const int* __restrict__ wt) {
    int idx = blockIdx.x * blockDim.x + threadIdx.x;    // group of 4 elements
    if (idx >= (N_DIM * K_DIM) / 4) return;
    int4 v = ((const int4*)wt)[idx];
    char4 c;
    c.x = (char)v.x; c.y = (char)v.y; c.z = (char)v.z; c.w = (char)v.w;
    ((char4*)g_w)[idx] = c;
}

// ---------------------------------------------------------------------------
// Block reductions (256 threads)
// ---------------------------------------------------------------------------
__device__ __forceinline__ float2 block_reduce_sum2(float a, float b, float* sh) {
    #pragma unroll
    for (int o = 16; o > 0; o >>= 1) {
        a += __shfl_xor_sync(0xFFFFFFFFu, a, o);
        b += __shfl_xor_sync(0xFFFFFFFFu, b, o);
    }
    int w = threadIdx.x >> 5, l = threadIdx.x & 31;
    if (l == 0) { sh[w] = a; sh[w + 8] = b; }
    __syncthreads();
    if (threadIdx.x < 32) {
        float va = (l < 8) ? sh[l] : 0.f;
        float vb = (l < 8) ? sh[l + 8] : 0.f;
        #pragma unroll
        for (int o = 4; o > 0; o >>= 1) {
            va += __shfl_xor_sync(0xFFFFFFFFu, va, o);
            vb += __shfl_xor_sync(0xFFFFFFFFu, vb, o);
        }
        if (l == 0) { sh[16] = va; sh[17] = vb; }
    }
    __syncthreads();
    float2 r = make_float2(sh[16], sh[17]);
    __syncthreads();
    return r;
}

__device__ __forceinline__ float block_reduce_max(float v, float* sh) {
    #pragma unroll
    for (int o = 16; o > 0; o >>= 1)
        v = fmaxf(v, __shfl_xor_sync(0xFFFFFFFFu, v, o));
    int w = threadIdx.x >> 5, l = threadIdx.x & 31;
    if (l == 0) sh[w] = v;
    __syncthreads();
    if (threadIdx.x < 32) {
        float m = (l < 8) ? sh[l] : -1e30f;
        #pragma unroll
        for (int o = 4; o > 0; o >>= 1)
            m = fmaxf(m, __shfl_xor_sync(0xFFFFFFFFu, m, o));
        if (l == 0) sh[16] = m;
    }
    __syncthreads();
    float r = sh[16];
    __syncthreads();
    return r;
}

// ---------------------------------------------------------------------------
// Kernel 1: fused input LayerNorm + per-token int8 absmax quantization.
// ---------------------------------------------------------------------------
__global__ __launch_bounds__(256) void ln_quant_kernel(const float* __restrict__ x) {
    __shared__ float sh[18];
    const int row = blockIdx.x;
    const int t = threadIdx.x;
    const float4* xr = (const float4*)(x + (size_t)row * K_DIM);

    float v[8];
    float4 a = xr[t];
    float4 b = xr[t + 256];
    v[0]=a.x; v[1]=a.y; v[2]=a.z; v[3]=a.w;
    v[4]=b.x; v[5]=b.y; v[6]=b.z; v[7]=b.w;

    float s = 0.f, ss = 0.f;
    #pragma unroll
    for (int i = 0; i < 8; i++) { s += v[i]; ss += v[i]*v[i]; }
    float2 tot = block_reduce_sum2(s, ss, sh);

    const float invn = 1.0f / (float)K_DIM;
    float mu  = tot.x * invn;
    float var = fmaxf(tot.y * invn - mu * mu, 0.f);   // biased variance (torch default)
    float rstd = rsqrtf(var + 1e-5f);

    float amax = 0.f;
    #pragma unroll
    for (int i = 0; i < 8; i++) {
        v[i] = (v[i] - mu) * rstd;
        amax = fmaxf(amax, fabsf(v[i]));
    }
    amax = block_reduce_max(amax, sh);
    amax = fmaxf(amax, 1e-5f);
    float scale = amax * (1.0f / 127.0f);
    float inv   = 127.0f / amax;

    char q[8];
    #pragma unroll
    for (int i = 0; i < 8; i++) {
        int qi = (int)rintf(v[i] * inv);       // round-half-even, matches jnp.round
        qi = max(-127, min(127, qi));
        q[i] = (char)qi;
    }
    char4* dst = (char4*)(g_xq + (size_t)row * K_DIM);
    char4 c0; c0.x=q[0]; c0.y=q[1]; c0.z=q[2]; c0.w=q[3];
    char4 c1; c1.x=q[4]; c1.y=q[5]; c1.z=q[6]; c1.w=q[7];
    dst[t] = c0;
    dst[t + 256] = c1;
    if (t == 0) g_xscale[row] = scale;
}

// ---------------------------------------------------------------------------
// Kernel 2: int8 tensor-core GEMM via mma.sync.m16n8k32.
// Tile 128x128x64B, 8 warps (2x4), warp tile 64x32, 3-stage cp.async pipeline.
// acc[m][n] = sum_k xq[m][k] * w[n][k]
// ---------------------------------------------------------------------------
#define BM  128
#define BN  128
#define BKB 64    // K-bytes per tile
#define NIT (K_DIM / BKB)   // 32
#define NSTAGE 3

__device__ __forceinline__ uint32_t smem_u32(const void* p) {
    uint32_t a;
    asm("{ .reg .u64 t; cvta.to.shared.u64 t, %1; cvt.u32.u64 %0, t; }" : "=r"(a) : "l"(p));
    return a;
}

// swizzled byte offset within a [128 rows x 64B] tile
__device__ __forceinline__ uint32_t swz(int row, int c) {
    return (uint32_t)(row * 64 + ((c ^ ((row >> 1) & 3)) << 4));
}

__device__ __forceinline__ void cp16(uint32_t saddr, const void* g) {
    asm volatile("cp.async.cg.shared.global [%0], [%1], 16;" :: "r"(saddr), "l"(g));
}

__device__ __forceinline__ void ldsm4(uint32_t* r, uint32_t addr) {
    asm volatile("ldmatrix.sync.aligned.m8n8.x4.shared.b16 {%0,%1,%2,%3}, [%4];"
                 : "=r"(r[0]), "=r"(r[1]), "=r"(r[2]), "=r"(r[3]) : "r"(addr));
}

__device__ __forceinline__ void mma_s8(int* c, const uint32_t* a, const uint32_t* b) {
    asm volatile(
        "mma.sync.aligned.m16n8k32.row.col.s32.s8.s8.s32 "
        "{%0,%1,%2,%3}, {%4,%5,%6,%7}, {%8,%9}, {%0,%1,%2,%3};"
        : "+r"(c[0]), "+r"(c[1]), "+r"(c[2]), "+r"(c[3])
        : "r"(a[0]), "r"(a[1]), "r"(a[2]), "r"(a[3]), "r"(b[0]), "r"(b[1]));
}

__global__ __launch_bounds__(256, 2) void gemm_kernel() {
    __shared__ uint8_t smA[NSTAGE][BM * 64];
    __shared__ uint8_t smB[NSTAGE][BN * 64];

    const int tid  = threadIdx.x;
    const int wid  = tid >> 5;
    const int lane = tid & 31;
    const int wm   = wid >> 2;          // 0..1 -> m offset wm*64
    const int wn   = wid & 3;           // 0..3 -> n offset wn*32
    const int bm   = (int)blockIdx.y * BM;
    const int bn   = (int)blockIdx.x * BN;

    int acc[4][4][4];
    #pragma unroll
    for (int i = 0; i < 4; i++)
        #pragma unroll
        for (int j = 0; j < 4; j++)
            #pragma unroll
            for (int r = 0; r < 4; r++) acc[i][j][r] = 0;

    // cooperative load of one stage: 512 A chunks + 512 B chunks of 16B
    auto load_stage = [&](int st, int k0) {
        uint32_t sa = smem_u32(smA[st]);
        uint32_t sb = smem_u32(smB[st]);
        #pragma unroll
        for (int i = 0; i < 2; i++) {
            int idx = tid + i * 256;        // 0..511
            int row = idx >> 2, c = idx & 3;
            uint32_t d = swz(row, c);
            cp16(sa + d, g_xq + (size_t)(bm + row) * K_DIM + k0 + c * 16);
            cp16(sb + d, g_w  + (size_t)(bn + row) * K_DIM + k0 + c * 16);
        }
    };

    // prologue: 2 stages in flight
    load_stage(0, 0);
    asm volatile("cp.async.commit_group;" ::: "memory");
    load_stage(1, BKB);
    asm volatile("cp.async.commit_group;" ::: "memory");

    const int lrow = lane & 15;         // ldmatrix row within 16
    const int lchk = lane >> 4;         // ldmatrix chunk select

    for (int it = 0; it < NIT; ++it) {
        asm volatile("cp.async.wait_group 1;" ::: "memory");
        __syncthreads();

        // issue next load (overwrites stage consumed 2 iters ago; sync above guards)
        int nt = it + 2;
        if (nt < NIT) load_stage(nt % NSTAGE, nt * BKB);
        asm volatile("cp.async.commit_group;" ::: "memory");

        const int st = it % NSTAGE;
        const uint32_t sa = smem_u32(smA[st]);
        const uint32_t sb = smem_u32(smB[st]);

        #pragma unroll
        for (int ks = 0; ks < 2; ks++) {    // two k32 steps per 64B tile
            uint32_t a[4][4];
            #pragma unroll
            for (int i = 0; i < 4; i++) {
                int row = wm * 64 + i * 16 + lrow;
                ldsm4(a[i], sa + swz(row, ks * 2 + lchk));
            }
            uint32_t b[4][2];
            #pragma unroll
            for (int jj = 0; jj < 2; jj++) {
                uint32_t r[4];
                int row = wn * 32 + jj * 16 + lrow;
                ldsm4(r, sb + swz(row, ks * 2 + lchk));
                b[jj*2][0]   = r[0]; b[jj*2][1]   = r[2];
                b[jj*2+1][0] = r[1]; b[jj*2+1][1] = r[3];
            }
            #pragma unroll
            for (int i = 0; i < 4; i++)
                #pragma unroll
                for (int j = 0; j < 4; j++)
                    mma_s8(acc[i][j], a[i], b[j]);
        }
    }

    // epilogue: direct int2 stores (8B, sector-aligned groups of 4 lanes)
    #pragma unroll
    for (int i = 0; i < 4; i++) {
        #pragma unroll
        for (int j = 0; j < 4; j++) {
            int r0  = bm + wm * 64 + i * 16 + (lane >> 2);
            int col = bn + wn * 32 + j * 8 + (lane & 3) * 2;
            int2 v0; v0.x = acc[i][j][0]; v0.y = acc[i][j][1];
            int2 v1; v1.x = acc[i][j][2]; v1.y = acc[i][j][3];
            *(int2*)(g_acc + (size_t)r0 * N_DIM + col)       = v0;
            *(int2*)(g_acc + (size_t)(r0 + 8) * N_DIM + col) = v1;
        }
    }
}

// ---------------------------------------------------------------------------
// Kernel 3: fused dequant (x_scale[t] * w_scale[o]) + output LayerNorm.
// ---------------------------------------------------------------------------
__global__ __launch_bounds__(256) void ln_out_kernel(const float* __restrict__ wscale,
                                                     float* __restrict__ out) {
    __shared__ float sh[18];
    const int row = blockIdx.x;
    const int t = threadIdx.x;
    const float s_t = g_xscale[row];

    const int4* ar = (const int4*)(g_acc + (size_t)row * N_DIM);
    const float4* ws = (const float4*)wscale;

    int4 a = ar[t];
    int4 b = ar[t + 256];
    float4 w0 = __ldg(&ws[t]);
    float4 w1 = __ldg(&ws[t + 256]);

    float v[8];
    v[0] = (float)a.x * s_t * w0.x;
    v[1] = (float)a.y * s_t * w0.y;
    v[2] = (float)a.z * s_t * w0.z;
    v[3] = (float)a.w * s_t * w0.w;
    v[4] = (float)b.x * s_t * w1.x;
    v[5] = (float)b.y * s_t * w1.y;
    v[6] = (float)b.z * s_t * w1.z;
    v[7] = (float)b.w * s_t * w1.w;

    float s = 0.f, ss = 0.f;
    #pragma unroll
    for (int i = 0; i < 8; i++) { s += v[i]; ss += v[i]*v[i]; }
    float2 tot = block_reduce_sum2(s, ss, sh);

    const float invn = 1.0f / (float)N_DIM;
    float mu  = tot.x * invn;
    float var = fmaxf(tot.y * invn - mu * mu, 0.f);
    float rstd = rsqrtf(var + 1e-5f);

    float4* dst = (float4*)(out + (size_t)row * N_DIM);
    float4 o0, o1;
    o0.x = (v[0]-mu)*rstd; o0.y = (v[1]-mu)*rstd;
    o0.z = (v[2]-mu)*rstd; o0.w = (v[3]-mu)*rstd;
    o1.x = (v[4]-mu)*rstd; o1.y = (v[5]-mu)*rstd;
    o1.z = (v[6]-mu)*rstd; o1.w = (v[7]-mu)*rstd;
    dst[t] = o0;
    dst[t + 256] = o1;
}

// ---------------------------------------------------------------------------
// Launch
// ---------------------------------------------------------------------------
extern "C" void kernel_launch(void* const* d_in, const int* in_sizes, int n_in,
                              void* d_out, int out_size) {
    const float* x  = (const float*)d_in[0];          // [4,4096,2048] f32
    const int*   wt = (const int*)d_in[1];            // [2048,2048] i32 ternary
    const float* ws = (const float*)d_in[2];          // [2048] f32
    float* out = (float*)d_out;                       // [4,4096,2048] f32

    pack_w_kernel<<<(N_DIM * K_DIM / 4 + 255) / 256, 256>>>(wt);
    ln_quant_kernel<<<M_TOK, 256>>>(x);
    dim3 grid(N_DIM / BN, M_TOK / BM);                // (16, 128)
    gemm_kernel<<<grid, 256>>>();
    ln_out_kernel<<<M_TOK, 256>>>(ws, out);
}

// round 5
// speedup vs baseline: 4.0154x; 1.0490x over previous
#include <cuda_runtime.h>
#include <cuda_bf16.h>
#include <cstdint>

#define M_TOK 16384   // B*S tokens
#define K_DIM 2048    // DIN
#define N_DIM 2048    // DOUT

// ---------------------------------------------------------------------------
// Scratch (__device__ globals; no allocations allowed)
// ---------------------------------------------------------------------------
__device__ int8_t g_xq[(size_t)M_TOK * K_DIM];      // 32 MB quantized activations
__device__ float  g_xscale[M_TOK];                  // per-token scale
__device__ int8_t g_w[(size_t)N_DIM * K_DIM];       // 4 MB ternary weights as int8
__device__ int    g_acc[(size_t)M_TOK * N_DIM];     // 128 MB int32 GEMM output

// ---------------------------------------------------------------------------
// Kernel 0: repack ternary int32 weights -> int8
// ---------------------------------------------------------------------------
__global__ void pack_w_kernel(const int* __restrict__ wt) {
    int idx = blockIdx.x * blockDim.x + threadIdx.x;    // group of 4 elements
    if (idx >= (N_DIM * K_DIM) / 4) return;
    int4 v = ((const int4*)wt)[idx];
    char4 c;
    c.x = (char)v.x; c.y = (char)v.y; c.z = (char)v.z; c.w = (char)v.w;
    ((char4*)g_w)[idx] = c;
}

// ---------------------------------------------------------------------------
// Block reductions (256 threads)
// ---------------------------------------------------------------------------
__device__ __forceinline__ float2 block_reduce_sum2(float a, float b, float* sh) {
    #pragma unroll
    for (int o = 16; o > 0; o >>= 1) {
        a += __shfl_xor_sync(0xFFFFFFFFu, a, o);
        b += __shfl_xor_sync(0xFFFFFFFFu, b, o);
    }
    int w = threadIdx.x >> 5, l = threadIdx.x & 31;
    if (l == 0) { sh[w] = a; sh[w + 8] = b; }
    __syncthreads();
    if (threadIdx.x < 32) {
        float va = (l < 8) ? sh[l] : 0.f;
        float vb = (l < 8) ? sh[l + 8] : 0.f;
        #pragma unroll
        for (int o = 4; o > 0; o >>= 1) {
            va += __shfl_xor_sync(0xFFFFFFFFu, va, o);
            vb += __shfl_xor_sync(0xFFFFFFFFu, vb, o);
        }
        if (l == 0) { sh[16] = va; sh[17] = vb; }
    }
    __syncthreads();
    float2 r = make_float2(sh[16], sh[17]);
    __syncthreads();
    return r;
}

__device__ __forceinline__ float block_reduce_max(float v, float* sh) {
    #pragma unroll
    for (int o = 16; o > 0; o >>= 1)
        v = fmaxf(v, __shfl_xor_sync(0xFFFFFFFFu, v, o));
    int w = threadIdx.x >> 5, l = threadIdx.x & 31;
    if (l == 0) sh[w] = v;
    __syncthreads();
    if (threadIdx.x < 32) {
        float m = (l < 8) ? sh[l] : -1e30f;
        #pragma unroll
        for (int o = 4; o > 0; o >>= 1)
            m = fmaxf(m, __shfl_xor_sync(0xFFFFFFFFu, m, o));
        if (l == 0) sh[16] = m;
    }
    __syncthreads();
    float r = sh[16];
    __syncthreads();
    return r;
}

// ---------------------------------------------------------------------------
// Kernel 1: fused input LayerNorm + per-token int8 absmax quantization.
// ---------------------------------------------------------------------------
__global__ __launch_bounds__(256) void ln_quant_kernel(const float* __restrict__ x) {
    __shared__ float sh[18];
    const int row = blockIdx.x;
    const int t = threadIdx.x;
    const float4* xr = (const float4*)(x + (size_t)row * K_DIM);

    float v[8];
    float4 a = xr[t];
    float4 b = xr[t + 256];
    v[0]=a.x; v[1]=a.y; v[2]=a.z; v[3]=a.w;
    v[4]=b.x; v[5]=b.y; v[6]=b.z; v[7]=b.w;

    float s = 0.f, ss = 0.f;
    #pragma unroll
    for (int i = 0; i < 8; i++) { s += v[i]; ss += v[i]*v[i]; }
    float2 tot = block_reduce_sum2(s, ss, sh);

    const float invn = 1.0f / (float)K_DIM;
    float mu  = tot.x * invn;
    float var = fmaxf(tot.y * invn - mu * mu, 0.f);   // biased variance (torch default)
    float rstd = rsqrtf(var + 1e-5f);

    float amax = 0.f;
    #pragma unroll
    for (int i = 0; i < 8; i++) {
        v[i] = (v[i] - mu) * rstd;
        amax = fmaxf(amax, fabsf(v[i]));
    }
    amax = block_reduce_max(amax, sh);
    amax = fmaxf(amax, 1e-5f);
    float scale = amax * (1.0f / 127.0f);
    float inv   = 127.0f / amax;

    char q[8];
    #pragma unroll
    for (int i = 0; i < 8; i++) {
        int qi = (int)rintf(v[i] * inv);       // round-half-even, matches jnp.round
        qi = max(-127, min(127, qi));
        q[i] = (char)qi;
    }
    char4* dst = (char4*)(g_xq + (size_t)row * K_DIM);
    char4 c0; c0.x=q[0]; c0.y=q[1]; c0.z=q[2]; c0.w=q[3];
    char4 c1; c1.x=q[4]; c1.y=q[5]; c1.z=q[6]; c1.w=q[7];
    dst[t] = c0;
    dst[t + 256] = c1;
    if (t == 0) g_xscale[row] = scale;
}

// ---------------------------------------------------------------------------
// Kernel 2: int8 tensor-core GEMM via mma.sync.m16n8k32.
// CTA tile 128x256, K staged 128B, 8 warps (2x4), warp tile 64x64,
// 3-stage cp.async pipeline.  acc[m][n] = sum_k xq[m][k] * w[n][k]
// ---------------------------------------------------------------------------
#define BM  128
#define BN  256
#define BKB 128   // K-bytes per stage
#define NIT (K_DIM / BKB)   // 16
#define NSTAGE 3
#define A_BYTES (BM * BKB)            // 16 KB
#define B_BYTES (BN * BKB)            // 32 KB
#define STAGE_BYTES (A_BYTES + B_BYTES)   // 48 KB
#define SMEM_DYN (NSTAGE * STAGE_BYTES)   // 144 KB

__device__ __forceinline__ uint32_t smem_u32(const void* p) {
    uint32_t a;
    asm("{ .reg .u64 t; cvta.to.shared.u64 t, %1; cvt.u32.u64 %0, t; }" : "=r"(a) : "l"(p));
    return a;
}

// swizzled byte offset within a [rows x 128B] tile
__device__ __forceinline__ uint32_t swz(int row, int c) {
    return (uint32_t)(row * 128 + ((c ^ (row & 7)) << 4));
}

__device__ __forceinline__ void cp16(uint32_t saddr, const void* g) {
    asm volatile("cp.async.cg.shared.global [%0], [%1], 16;" :: "r"(saddr), "l"(g));
}

__device__ __forceinline__ void ldsm4(uint32_t* r, uint32_t addr) {
    asm volatile("ldmatrix.sync.aligned.m8n8.x4.shared.b16 {%0,%1,%2,%3}, [%4];"
                 : "=r"(r[0]), "=r"(r[1]), "=r"(r[2]), "=r"(r[3]) : "r"(addr));
}

__device__ __forceinline__ void mma_s8(int* c, const uint32_t* a, const uint32_t* b) {
    asm volatile(
        "mma.sync.aligned.m16n8k32.row.col.s32.s8.s8.s32 "
        "{%0,%1,%2,%3}, {%4,%5,%6,%7}, {%8,%9}, {%0,%1,%2,%3};"
        : "+r"(c[0]), "+r"(c[1]), "+r"(c[2]), "+r"(c[3])
        : "r"(a[0]), "r"(a[1]), "r"(a[2]), "r"(a[3]), "r"(b[0]), "r"(b[1]));
}

__global__ __launch_bounds__(256, 1) void gemm_kernel() {
    extern __shared__ uint8_t smem[];

    const int tid  = threadIdx.x;
    const int wid  = tid >> 5;
    const int lane = tid & 31;
    const int wm   = wid >> 2;          // 0..1 -> m offset wm*64
    const int wn   = wid & 3;           // 0..3 -> n offset wn*64
    const int bm   = (int)blockIdx.y * BM;
    const int bn   = (int)blockIdx.x * BN;
    const uint32_t sbase = smem_u32(smem);

    int acc[4][8][4];
    #pragma unroll
    for (int i = 0; i < 4; i++)
        #pragma unroll
        for (int j = 0; j < 8; j++)
            #pragma unroll
            for (int r = 0; r < 4; r++) acc[i][j][r] = 0;

    // cooperative load of one stage: A 1024 + B 2048 chunks of 16B = 12/thread
    auto load_stage = [&](int st, int k0) {
        uint32_t sa = sbase + st * STAGE_BYTES;
        uint32_t sb = sa + A_BYTES;
        #pragma unroll
        for (int i = 0; i < 12; i++) {
            int idx = tid + i * 256;        // 0..3071
            if (idx < 1024) {
                int row = idx >> 3, c = idx & 7;
                cp16(sa + swz(row, c), g_xq + (size_t)(bm + row) * K_DIM + k0 + c * 16);
            } else {
                int j = idx - 1024;
                int row = j >> 3, c = j & 7;
                cp16(sb + swz(row, c), g_w + (size_t)(bn + row) * K_DIM + k0 + c * 16);
            }
        }
    };

    // prologue: 2 stages in flight
    load_stage(0, 0);
    asm volatile("cp.async.commit_group;" ::: "memory");
    load_stage(1, BKB);
    asm volatile("cp.async.commit_group;" ::: "memory");

    const int lrow = lane & 15;         // ldmatrix row within 16
    const int lchk = lane >> 4;         // ldmatrix chunk select

    for (int it = 0; it < NIT; ++it) {
        asm volatile("cp.async.wait_group 1;" ::: "memory");
        __syncthreads();

        // issue next load (overwrites stage consumed 2 iters ago; sync above guards)
        int nt = it + 2;
        if (nt < NIT) load_stage(nt % NSTAGE, nt * BKB);
        asm volatile("cp.async.commit_group;" ::: "memory");

        const int st = it % NSTAGE;
        const uint32_t sa = sbase + st * STAGE_BYTES;
        const uint32_t sb = sa + A_BYTES;

        #pragma unroll
        for (int ks = 0; ks < 4; ks++) {    // four k32 steps per 128B stage
            uint32_t a[4][4];
            #pragma unroll
            for (int i = 0; i < 4; i++) {
                int row = wm * 64 + i * 16 + lrow;
                ldsm4(a[i], sa + swz(row, ks * 2 + lchk));
            }
            uint32_t b[8][2];
            #pragma unroll
            for (int jj = 0; jj < 4; jj++) {
                uint32_t r[4];
                int row = wn * 64 + jj * 16 + lrow;
                ldsm4(r, sb + swz(row, ks * 2 + lchk));
                b[jj*2][0]   = r[0]; b[jj*2][1]   = r[2];
                b[jj*2+1][0] = r[1]; b[jj*2+1][1] = r[3];
            }
            #pragma unroll
            for (int i = 0; i < 4; i++)
                #pragma unroll
                for (int j = 0; j < 8; j++)
                    mma_s8(acc[i][j], a[i], b[j]);
        }
    }

    // epilogue: direct int2 stores (8B, sector-aligned groups of 4 lanes)
    #pragma unroll
    for (int i = 0; i < 4; i++) {
        #pragma unroll
        for (int j = 0; j < 8; j++) {
            int r0  = bm + wm * 64 + i * 16 + (lane >> 2);
            int col = bn + wn * 64 + j * 8 + (lane & 3) * 2;
            int2 v0; v0.x = acc[i][j][0]; v0.y = acc[i][j][1];
            int2 v1; v1.x = acc[i][j][2]; v1.y = acc[i][j][3];
            *(int2*)(g_acc + (size_t)r0 * N_DIM + col)       = v0;
            *(int2*)(g_acc + (size_t)(r0 + 8) * N_DIM + col) = v1;
        }
    }
}

// ---------------------------------------------------------------------------
// Kernel 3: fused dequant (x_scale[t] * w_scale[o]) + output LayerNorm.
// ---------------------------------------------------------------------------
__global__ __launch_bounds__(256) void ln_out_kernel(const float* __restrict__ wscale,
                                                     float* __restrict__ out) {
    __shared__ float sh[18];
    const int row = blockIdx.x;
    const int t = threadIdx.x;
    const float s_t = g_xscale[row];

    const int4* ar = (const int4*)(g_acc + (size_t)row * N_DIM);
    const float4* ws = (const float4*)wscale;

    int4 a = ar[t];
    int4 b = ar[t + 256];
    float4 w0 = __ldg(&ws[t]);
    float4 w1 = __ldg(&ws[t + 256]);

    float v[8];
    v[0] = (float)a.x * s_t * w0.x;
    v[1] = (float)a.y * s_t * w0.y;
    v[2] = (float)a.z * s_t * w0.z;
    v[3] = (float)a.w * s_t * w0.w;
    v[4] = (float)b.x * s_t * w1.x;
    v[5] = (float)b.y * s_t * w1.y;
    v[6] = (float)b.z * s_t * w1.z;
    v[7] = (float)b.w * s_t * w1.w;

    float s = 0.f, ss = 0.f;
    #pragma unroll
    for (int i = 0; i < 8; i++) { s += v[i]; ss += v[i]*v[i]; }
    float2 tot = block_reduce_sum2(s, ss, sh);

    const float invn = 1.0f / (float)N_DIM;
    float mu  = tot.x * invn;
    float var = fmaxf(tot.y * invn - mu * mu, 0.f);
    float rstd = rsqrtf(var + 1e-5f);

    float4* dst = (float4*)(out + (size_t)row * N_DIM);
    float4 o0, o1;
    o0.x = (v[0]-mu)*rstd; o0.y = (v[1]-mu)*rstd;
    o0.z = (v[2]-mu)*rstd; o0.w = (v[3]-mu)*rstd;
    o1.x = (v[4]-mu)*rstd; o1.y = (v[5]-mu)*rstd;
    o1.z = (v[6]-mu)*rstd; o1.w = (v[7]-mu)*rstd;
    dst[t] = o0;
    dst[t + 256] = o1;
}

// ---------------------------------------------------------------------------
// Launch
// ---------------------------------------------------------------------------
extern "C" void kernel_launch(void* const* d_in, const int* in_sizes, int n_in,
                              void* d_out, int out_size) {
    const float* x  = (const float*)d_in[0];          // [4,4096,2048] f32
    const int*   wt = (const int*)d_in[1];            // [2048,2048] i32 ternary
    const float* ws = (const float*)d_in[2];          // [2048] f32
    float* out = (float*)d_out;                       // [4,4096,2048] f32

    cudaFuncSetAttribute(gemm_kernel, cudaFuncAttributeMaxDynamicSharedMemorySize, SMEM_DYN);

    pack_w_kernel<<<(N_DIM * K_DIM / 4 + 255) / 256, 256>>>(wt);
    ln_quant_kernel<<<M_TOK, 256>>>(x);
    dim3 grid(N_DIM / BN, M_TOK / BM);                // (8, 128)
    gemm_kernel<<<grid, 256, SMEM_DYN>>>();
    ln_out_kernel<<<M_TOK, 256>>>(ws, out);
}

// round 7
// speedup vs baseline: 4.1036x; 1.0220x over previous
#include <cuda_runtime.h>
#include <cuda_bf16.h>
#include <cstdint>

#define M_TOK 16384   // B*S tokens
#define K_DIM 2048    // DIN
#define N_DIM 2048    // DOUT

// ---------------------------------------------------------------------------
// Scratch (__device__ globals; no allocations allowed)
// ---------------------------------------------------------------------------
__device__ int8_t g_xq[(size_t)M_TOK * K_DIM];      // 32 MB quantized activations
__device__ float  g_xscale[M_TOK];                  // per-token scale
__device__ int8_t g_w[(size_t)N_DIM * K_DIM];       // 4 MB ternary weights as int8
__device__ int    g_acc[(size_t)M_TOK * N_DIM];     // 128 MB int32 GEMM output

// ---------------------------------------------------------------------------
// Kernel 0: repack ternary int32 weights -> int8
// ---------------------------------------------------------------------------
__global__ void pack_w_kernel(const int* __restrict__ wt) {
    int idx = blockIdx.x * blockDim.x + threadIdx.x;    // group of 4 elements
    if (idx >= (N_DIM * K_DIM) / 4) return;
    int4 v = __ldcs(&((const int4*)wt)[idx]);
    char4 c;
    c.x = (char)v.x; c.y = (char)v.y; c.z = (char)v.z; c.w = (char)v.w;
    ((char4*)g_w)[idx] = c;
}

// ---------------------------------------------------------------------------
// Block reductions (256 threads)
// ---------------------------------------------------------------------------
__device__ __forceinline__ float2 block_reduce_sum2(float a, float b, float* sh) {
    #pragma unroll
    for (int o = 16; o > 0; o >>= 1) {
        a += __shfl_xor_sync(0xFFFFFFFFu, a, o);
        b += __shfl_xor_sync(0xFFFFFFFFu, b, o);
    }
    int w = threadIdx.x >> 5, l = threadIdx.x & 31;
    if (l == 0) { sh[w] = a; sh[w + 8] = b; }
    __syncthreads();
    if (threadIdx.x < 32) {
        float va = (l < 8) ? sh[l] : 0.f;
        float vb = (l < 8) ? sh[l + 8] : 0.f;
        #pragma unroll
        for (int o = 4; o > 0; o >>= 1) {
            va += __shfl_xor_sync(0xFFFFFFFFu, va, o);
            vb += __shfl_xor_sync(0xFFFFFFFFu, vb, o);
        }
        if (l == 0) { sh[16] = va; sh[17] = vb; }
    }
    __syncthreads();
    float2 r = make_float2(sh[16], sh[17]);
    __syncthreads();
    return r;
}

__device__ __forceinline__ float block_reduce_max(float v, float* sh) {
    #pragma unroll
    for (int o = 16; o > 0; o >>= 1)
        v = fmaxf(v, __shfl_xor_sync(0xFFFFFFFFu, v, o));
    int w = threadIdx.x >> 5, l = threadIdx.x & 31;
    if (l == 0) sh[w] = v;
    __syncthreads();
    if (threadIdx.x < 32) {
        float m = (l < 8) ? sh[l] : -1e30f;
        #pragma unroll
        for (int o = 4; o > 0; o >>= 1)
            m = fmaxf(m, __shfl_xor_sync(0xFFFFFFFFu, m, o));
        if (l == 0) sh[16] = m;
    }
    __syncthreads();
    float r = sh[16];
    __syncthreads();
    return r;
}

// ---------------------------------------------------------------------------
// Kernel 1: fused input LayerNorm + per-token int8 absmax quantization.
// ---------------------------------------------------------------------------
__global__ __launch_bounds__(256) void ln_quant_kernel(const float* __restrict__ x) {
    __shared__ float sh[18];
    const int row = blockIdx.x;
    const int t = threadIdx.x;
    const float4* xr = (const float4*)(x + (size_t)row * K_DIM);

    float v[8];
    float4 a = __ldcs(&xr[t]);
    float4 b = __ldcs(&xr[t + 256]);
    v[0]=a.x; v[1]=a.y; v[2]=a.z; v[3]=a.w;
    v[4]=b.x; v[5]=b.y; v[6]=b.z; v[7]=b.w;

    float s = 0.f, ss = 0.f;
    #pragma unroll
    for (int i = 0; i < 8; i++) { s += v[i]; ss += v[i]*v[i]; }
    float2 tot = block_reduce_sum2(s, ss, sh);

    const float invn = 1.0f / (float)K_DIM;
    float mu  = tot.x * invn;
    float var = fmaxf(tot.y * invn - mu * mu, 0.f);   // biased variance (torch default)
    float rstd = rsqrtf(var + 1e-5f);

    float amax = 0.f;
    #pragma unroll
    for (int i = 0; i < 8; i++) {
        v[i] = (v[i] - mu) * rstd;
        amax = fmaxf(amax, fabsf(v[i]));
    }
    amax = block_reduce_max(amax, sh);
    amax = fmaxf(amax, 1e-5f);
    float scale = amax * (1.0f / 127.0f);
    float inv   = 127.0f / amax;

    char q[8];
    #pragma unroll
    for (int i = 0; i < 8; i++) {
        int qi = (int)rintf(v[i] * inv);       // round-half-even, matches jnp.round
        qi = max(-127, min(127, qi));
        q[i] = (char)qi;
    }
    char4* dst = (char4*)(g_xq + (size_t)row * K_DIM);
    char4 c0; c0.x=q[0]; c0.y=q[1]; c0.z=q[2]; c0.w=q[3];
    char4 c1; c1.x=q[4]; c1.y=q[5]; c1.z=q[6]; c1.w=q[7];
    dst[t] = c0;
    dst[t + 256] = c1;
    if (t == 0) g_xscale[row] = scale;
}

// ---------------------------------------------------------------------------
// Kernel 2: int8 tensor-core GEMM via mma.sync.m16n8k32.
// CTA tile 128x256, K staged 128B, 8 warps (2x4), warp tile 64x64,
// 4-stage cp.async pipeline.  acc[m][n] = sum_k xq[m][k] * w[n][k]
// Launched as two sequential M-slices (888 + 136 CTAs; same total wave count).
// ---------------------------------------------------------------------------
#define BM  128
#define BN  256
#define BKB 128   // K-bytes per stage
#define NIT (K_DIM / BKB)   // 16
#define NSTAGE 4
#define A_BYTES (BM * BKB)                // 16 KB
#define B_BYTES (BN * BKB)                // 32 KB
#define STAGE_BYTES (A_BYTES + B_BYTES)   // 48 KB
#define SMEM_DYN (NSTAGE * STAGE_BYTES)   // 192 KB

__device__ __forceinline__ uint32_t smem_u32(const void* p) {
    uint32_t a;
    asm("{ .reg .u64 t; cvta.to.shared.u64 t, %1; cvt.u32.u64 %0, t; }" : "=r"(a) : "l"(p));
    return a;
}

// swizzled byte offset within a [rows x 128B] tile
__device__ __forceinline__ uint32_t swz(int row, int c) {
    return (uint32_t)(row * 128 + ((c ^ (row & 7)) << 4));
}

__device__ __forceinline__ void cp16(uint32_t saddr, const void* g) {
    asm volatile("cp.async.cg.shared.global [%0], [%1], 16;" :: "r"(saddr), "l"(g));
}

__device__ __forceinline__ void ldsm4(uint32_t* r, uint32_t addr) {
    asm volatile("ldmatrix.sync.aligned.m8n8.x4.shared.b16 {%0,%1,%2,%3}, [%4];"
                 : "=r"(r[0]), "=r"(r[1]), "=r"(r[2]), "=r"(r[3]) : "r"(addr));
}

__device__ __forceinline__ void mma_s8(int* c, const uint32_t* a, const uint32_t* b) {
    asm volatile(
        "mma.sync.aligned.m16n8k32.row.col.s32.s8.s8.s32 "
        "{%0,%1,%2,%3}, {%4,%5,%6,%7}, {%8,%9}, {%0,%1,%2,%3};"
        : "+r"(c[0]), "+r"(c[1]), "+r"(c[2]), "+r"(c[3])
        : "r"(a[0]), "r"(a[1]), "r"(a[2]), "r"(a[3]), "r"(b[0]), "r"(b[1]));
}

__global__ __launch_bounds__(256, 1) void gemm_kernel(int m0) {
    extern __shared__ uint8_t smem[];

    const int tid  = threadIdx.x;
    const int wid  = tid >> 5;
    const int lane = tid & 31;
    const int wm   = wid >> 2;          // 0..1 -> m offset wm*64
    const int wn   = wid & 3;           // 0..3 -> n offset wn*64
    const int bm   = m0 + (int)blockIdx.y * BM;
    const int bn   = (int)blockIdx.x * BN;
    const uint32_t sbase = smem_u32(smem);

    int acc[4][8][4];
    #pragma unroll
    for (int i = 0; i < 4; i++)
        #pragma unroll
        for (int j = 0; j < 8; j++)
            #pragma unroll
            for (int r = 0; r < 4; r++) acc[i][j][r] = 0;

    // cooperative load of one stage: A 1024 + B 2048 chunks of 16B = 12/thread
    auto load_stage = [&](int st, int k0) {
        uint32_t sa = sbase + st * STAGE_BYTES;
        uint32_t sb = sa + A_BYTES;
        #pragma unroll
        for (int i = 0; i < 12; i++) {
            int idx = tid + i * 256;        // 0..3071
            if (idx < 1024) {
                int row = idx >> 3, c = idx & 7;
                cp16(sa + swz(row, c), g_xq + (size_t)(bm + row) * K_DIM + k0 + c * 16);
            } else {
                int j = idx - 1024;
                int row = j >> 3, c = j & 7;
                cp16(sb + swz(row, c), g_w + (size_t)(bn + row) * K_DIM + k0 + c * 16);
            }
        }
    };

    // prologue: 3 stages in flight
    load_stage(0, 0);
    asm volatile("cp.async.commit_group;" ::: "memory");
    load_stage(1, BKB);
    asm volatile("cp.async.commit_group;" ::: "memory");
    load_stage(2, 2 * BKB);
    asm volatile("cp.async.commit_group;" ::: "memory");

    const int lrow = lane & 15;         // ldmatrix row within 16
    const int lchk = lane >> 4;         // ldmatrix chunk select

    for (int it = 0; it < NIT; ++it) {
        asm volatile("cp.async.wait_group 2;" ::: "memory");
        __syncthreads();

        // issue next load (overwrites stage consumed last iter; sync above guards)
        int nt = it + 3;
        if (nt < NIT) load_stage(nt % NSTAGE, nt * BKB);
        asm volatile("cp.async.commit_group;" ::: "memory");

        const int st = it % NSTAGE;
        const uint32_t sa = sbase + st * STAGE_BYTES;
        const uint32_t sb = sa + A_BYTES;

        #pragma unroll
        for (int ks = 0; ks < 4; ks++) {    // four k32 steps per 128B stage
            uint32_t a[4][4];
            #pragma unroll
            for (int i = 0; i < 4; i++) {
                int row = wm * 64 + i * 16 + lrow;
                ldsm4(a[i], sa + swz(row, ks * 2 + lchk));
            }
            uint32_t b[8][2];
            #pragma unroll
            for (int jj = 0; jj < 4; jj++) {
                uint32_t r[4];
                int row = wn * 64 + jj * 16 + lrow;
                ldsm4(r, sb + swz(row, ks * 2 + lchk));
                b[jj*2][0]   = r[0]; b[jj*2][1]   = r[2];
                b[jj*2+1][0] = r[1]; b[jj*2+1][1] = r[3];
            }
            #pragma unroll
            for (int i = 0; i < 4; i++)
                #pragma unroll
                for (int j = 0; j < 8; j++)
                    mma_s8(acc[i][j], a[i], b[j]);
        }
    }

    // epilogue: direct int2 streaming stores (acc has no reuse until ln_out)
    #pragma unroll
    for (int i = 0; i < 4; i++) {
        #pragma unroll
        for (int j = 0; j < 8; j++) {
            int r0  = bm + wm * 64 + i * 16 + (lane >> 2);
            int col = bn + wn * 64 + j * 8 + (lane & 3) * 2;
            int2 v0; v0.x = acc[i][j][0]; v0.y = acc[i][j][1];
            int2 v1; v1.x = acc[i][j][2]; v1.y = acc[i][j][3];
            __stcs((int2*)(g_acc + (size_t)r0 * N_DIM + col), v0);
            __stcs((int2*)(g_acc + (size_t)(r0 + 8) * N_DIM + col), v1);
        }
    }
}

// ---------------------------------------------------------------------------
// Kernel 3: fused dequant (x_scale[t] * w_scale[o]) + output LayerNorm.
// ---------------------------------------------------------------------------
__global__ __launch_bounds__(256) void ln_out_kernel(const float* __restrict__ wscale,
                                                     float* __restrict__ out) {
    __shared__ float sh[18];
    const int row = blockIdx.x;
    const int t = threadIdx.x;
    const float s_t = g_xscale[row];

    const int4* ar = (const int4*)(g_acc + (size_t)row * N_DIM);
    const float4* ws = (const float4*)wscale;

    int4 a = __ldcs(&ar[t]);
    int4 b = __ldcs(&ar[t + 256]);
    float4 w0 = __ldg(&ws[t]);
    float4 w1 = __ldg(&ws[t + 256]);

    float v[8];
    v[0] = (float)a.x * s_t * w0.x;
    v[1] = (float)a.y * s_t * w0.y;
    v[2] = (float)a.z * s_t * w0.z;
    v[3] = (float)a.w * s_t * w0.w;
    v[4] = (float)b.x * s_t * w1.x;
    v[5] = (float)b.y * s_t * w1.y;
    v[6] = (float)b.z * s_t * w1.z;
    v[7] = (float)b.w * s_t * w1.w;

    float s = 0.f, ss = 0.f;
    #pragma unroll
    for (int i = 0; i < 8; i++) { s += v[i]; ss += v[i]*v[i]; }
    float2 tot = block_reduce_sum2(s, ss, sh);

    const float invn = 1.0f / (float)N_DIM;
    float mu  = tot.x * invn;
    float var = fmaxf(tot.y * invn - mu * mu, 0.f);
    float rstd = rsqrtf(var + 1e-5f);

    float4* dst = (float4*)(out + (size_t)row * N_DIM);
    float4 o0, o1;
    o0.x = (v[0]-mu)*rstd; o0.y = (v[1]-mu)*rstd;
    o0.z = (v[2]-mu)*rstd; o0.w = (v[3]-mu)*rstd;
    o1.x = (v[4]-mu)*rstd; o1.y = (v[5]-mu)*rstd;
    o1.z = (v[6]-mu)*rstd; o1.w = (v[7]-mu)*rstd;
    __stcs(&dst[t], o0);
    __stcs(&dst[t + 256], o1);
}

// ---------------------------------------------------------------------------
// Launch (single stream; GEMM split 888 + 136 CTAs = identical wave count)
// ---------------------------------------------------------------------------
extern "C" void kernel_launch(void* const* d_in, const int* in_sizes, int n_in,
                              void* d_out, int out_size) {
    const float* x  = (const float*)d_in[0];          // [4,4096,2048] f32
    const int*   wt = (const int*)d_in[1];            // [2048,2048] i32 ternary
    const float* ws = (const float*)d_in[2];          // [2048] f32
    float* out = (float*)d_out;                       // [4,4096,2048] f32

    cudaFuncSetAttribute(gemm_kernel, cudaFuncAttributeMaxDynamicSharedMemorySize, SMEM_DYN);

    pack_w_kernel<<<(N_DIM * K_DIM / 4 + 255) / 256, 256>>>(wt);
    ln_quant_kernel<<<M_TOK, 256>>>(x);

    dim3 grid1(N_DIM / BN, 111);   // 888 CTAs: rows 0..14207
    dim3 grid2(N_DIM / BN, 17);    // 136 CTAs: rows 14208..16383
    gemm_kernel<<<grid1, 256, SMEM_DYN>>>(0);
    gemm_kernel<<<grid2, 256, SMEM_DYN>>>(111 * BM);

    ln_out_kernel<<<M_TOK, 256>>>(ws, out);
}